// round 5
// baseline (speedup 1.0000x reference)
#include <cuda_runtime.h>
#include <cstdint>

#define N_NODES 100000
#define E_MAX   1600000
#define HID     128
#define NB_SCAN 128
#define GBM 128
#define GBK 32
#define ILV 17   // 1 gemm block + 16 spmm blocks per group

typedef unsigned long long u64t;

// ---------------- device scratch (no allocations allowed) ----------------
__device__ int   g_deg[N_NODES];
__device__ int   g_rowptr[N_NODES + 1];
__device__ int   g_fill[N_NODES];
__device__ int   g_bsum[NB_SCAN];
__device__ int   g_boff[NB_SCAN];
__device__ int   g_col[E_MAX];
__device__ float g_dinv[N_NODES];
__device__ float g_tx1[(size_t)N_NODES * HID];
__device__ float g_h1 [(size_t)N_NODES * HID];
__device__ float g_h2 [(size_t)N_NODES * HID];
__device__ float g_hg [64 * HID];

// ---------------- packed f32x2 helpers ----------------
__device__ __forceinline__ void ffma2(u64t &d, u64t a, u64t b) {
    asm("fma.rn.f32x2 %0, %1, %2, %0;" : "+l"(d) : "l"(a), "l"(b));
}
__device__ __forceinline__ u64t dup2(float x) {
    u64t r; asm("mov.b64 %0, {%1, %1};" : "=l"(r) : "f"(x)); return r;
}
__device__ __forceinline__ float2 unpack2(u64t v) {
    float2 f; asm("mov.b64 {%0, %1}, %2;" : "=f"(f.x), "=f"(f.y) : "l"(v)); return f;
}

// ---------------- prep ----------------
__global__ void k_zero_deg(int n) {
    int i = blockIdx.x * blockDim.x + threadIdx.x;
    if (i < n) g_deg[i] = 0;
}

__global__ void k_hist(const int* __restrict__ dst, int e) {
    int i = blockIdx.x * blockDim.x + threadIdx.x;
    if (i < e) atomicAdd(&g_deg[dst[i]], 1);
}

__global__ void k_scanA(int n) {
    __shared__ int s[1024];
    int tid = threadIdx.x;
    int i = blockIdx.x * 1024 + tid;
    int v = (i < n) ? g_deg[i] : 0;
    s[tid] = v;
    __syncthreads();
    for (int off = 1; off < 1024; off <<= 1) {
        int t = (tid >= off) ? s[tid - off] : 0;
        __syncthreads();
        s[tid] += t;
        __syncthreads();
    }
    if (i < n) g_rowptr[i] = s[tid] - v;
    if (tid == 1023) g_bsum[blockIdx.x] = s[1023];
}

__global__ void k_scanB(int nb) {
    __shared__ int s[NB_SCAN];
    int tid = threadIdx.x;
    int v = (tid < nb) ? g_bsum[tid] : 0;
    s[tid] = v;
    __syncthreads();
    for (int off = 1; off < NB_SCAN; off <<= 1) {
        int t = (tid >= off) ? s[tid - off] : 0;
        __syncthreads();
        s[tid] += t;
        __syncthreads();
    }
    s[tid] -= v;
    g_boff[tid] = s[tid];
}

__global__ void k_scanC(int n, int e) {
    int i = blockIdx.x * 1024 + threadIdx.x;
    if (i < n) {
        int rp = g_rowptr[i] + g_boff[i >> 10];
        g_rowptr[i] = rp;
        g_fill[i]   = rp;
        g_dinv[i]   = rsqrtf(fmaxf((float)g_deg[i], 1.0f));
        if (i == n - 1) g_rowptr[n] = e;
    }
}

__global__ void k_fill(const int* __restrict__ src, const int* __restrict__ dst, int e) {
    int i = blockIdx.x * blockDim.x + threadIdx.x;
    if (i < e) {
        int p = atomicAdd(&g_fill[dst[i]], 1);
        g_col[p] = src[i];
    }
}

// ---------------- Phase A: interleaved [GEMM-top | SpMM] ----------------
// All device-global selection happens INSIDE the kernel via `layer`.
// layer 0: Afeat = xin,  C = g_h1
// layer 1: Afeat = g_h1, C = g_h2
// grid = nGemm * ILV; per group of ILV blocks: r==0 GEMM tile, r>0 SpMM blocks.
__global__ __launch_bounds__(256) void k_phaseA(int layer,
                                                const float* __restrict__ xin,
                                                const float* __restrict__ Wtop,
                                                const float* __restrict__ bias,
                                                int n, int nSpmm) {
    const float* __restrict__ Afeat = (layer == 0) ? xin : g_h1;
    float* __restrict__ C = (layer == 0) ? g_h1 : g_h2;

    int grp = blockIdx.x / ILV;
    int r   = blockIdx.x % ILV;

    if (r != 0) {
        // ---- SpMM role ----
        int sblk = grp * (ILV - 1) + (r - 1);
        if (sblk >= nSpmm) return;
        int row = sblk * 8 + (threadIdx.x >> 5);
        if (row >= n) return;
        int lane = threadIdx.x & 31;
        int e0 = g_rowptr[row];
        int e1 = g_rowptr[row + 1];
        float4 acc = make_float4(0.f, 0.f, 0.f, 0.f);
        for (int e = e0; e < e1; e++) {
            int s = g_col[e];
            float w = g_dinv[s];
            float4 v = *(const float4*)&Afeat[(size_t)s * HID + lane * 4];
            acc.x += w * v.x;
            acc.y += w * v.y;
            acc.z += w * v.z;
            acc.w += w * v.w;
        }
        float sc = -g_dinv[row];
        acc.x *= sc; acc.y *= sc; acc.z *= sc; acc.w *= sc;
        *(float4*)&g_tx1[(size_t)row * HID + lane * 4] = acc;
        return;
    }

    // ---- GEMM role: C = Afeat @ Wtop + bias (K=128, no relu) ----
    __shared__ float As[GBK][GBM];
    __shared__ float Ws[GBK][HID];

    int tid = threadIdx.x;
    int bm = grp * GBM;
    int tx = tid & 15;
    int ty = tid >> 4;

    u64t acc2[8][4];
#pragma unroll
    for (int i = 0; i < 8; i++)
#pragma unroll
        for (int j = 0; j < 4; j++) acc2[i][j] = 0ull;

    int ar = tid >> 3;
    int ak = (tid & 7) * 4;
    int wr = tid >> 5;
    int wn = (tid & 31) * 4;

    for (int k0 = 0; k0 < HID; k0 += GBK) {
#pragma unroll
        for (int p = 0; p < 4; p++) {
            int row = bm + ar + p * 32;
            float4 v = make_float4(0.f, 0.f, 0.f, 0.f);
            if (row < n) v = *(const float4*)&Afeat[(size_t)row * HID + k0 + ak];
            As[ak + 0][ar + p * 32] = v.x;
            As[ak + 1][ar + p * 32] = v.y;
            As[ak + 2][ar + p * 32] = v.z;
            As[ak + 3][ar + p * 32] = v.w;
        }
#pragma unroll
        for (int p = 0; p < 4; p++) {
            *(float4*)&Ws[wr + p * 8][wn] = *(const float4*)&Wtop[(size_t)(k0 + wr + p * 8) * HID + wn];
        }
        __syncthreads();

#pragma unroll
        for (int kk = 0; kk < GBK; kk++) {
            float a[8];
            u64t b2[4];
            *(float4*)(a)     = *(const float4*)&As[kk][ty * 8];
            *(float4*)(a + 4) = *(const float4*)&As[kk][ty * 8 + 4];
            ulonglong2 t0 = *(const ulonglong2*)&Ws[kk][tx * 8];
            ulonglong2 t1 = *(const ulonglong2*)&Ws[kk][tx * 8 + 4];
            b2[0] = t0.x; b2[1] = t0.y; b2[2] = t1.x; b2[3] = t1.y;
#pragma unroll
            for (int i = 0; i < 8; i++) {
                u64t ad = dup2(a[i]);
#pragma unroll
                for (int j = 0; j < 4; j++) ffma2(acc2[i][j], ad, b2[j]);
            }
        }
        __syncthreads();
    }

#pragma unroll
    for (int i = 0; i < 8; i++) {
        int row = bm + ty * 8 + i;
        if (row < n) {
#pragma unroll
            for (int j = 0; j < 4; j++) {
                float2 f = unpack2(acc2[i][j]);
                int col = tx * 8 + j * 2;
                C[(size_t)row * HID + col]     = f.x + bias[col];
                C[(size_t)row * HID + col + 1] = f.y + bias[col + 1];
            }
        }
    }
}

// ---------------- Phase B: C = relu(C + g_tx1 @ Wbot) ----------------
__global__ __launch_bounds__(256) void k_phaseB(int layer,
                                                const float* __restrict__ Wbot,
                                                int n) {
    float* __restrict__ C = (layer == 0) ? g_h1 : g_h2;

    __shared__ float As[GBK][GBM];
    __shared__ float Ws[GBK][HID];

    int tid = threadIdx.x;
    int bm = blockIdx.x * GBM;
    int tx = tid & 15;
    int ty = tid >> 4;

    u64t acc2[8][4];
#pragma unroll
    for (int i = 0; i < 8; i++)
#pragma unroll
        for (int j = 0; j < 4; j++) acc2[i][j] = 0ull;

    int ar = tid >> 3;
    int ak = (tid & 7) * 4;
    int wr = tid >> 5;
    int wn = (tid & 31) * 4;

    for (int k0 = 0; k0 < HID; k0 += GBK) {
#pragma unroll
        for (int p = 0; p < 4; p++) {
            int row = bm + ar + p * 32;
            float4 v = make_float4(0.f, 0.f, 0.f, 0.f);
            if (row < n) v = *(const float4*)&g_tx1[(size_t)row * HID + k0 + ak];
            As[ak + 0][ar + p * 32] = v.x;
            As[ak + 1][ar + p * 32] = v.y;
            As[ak + 2][ar + p * 32] = v.z;
            As[ak + 3][ar + p * 32] = v.w;
        }
#pragma unroll
        for (int p = 0; p < 4; p++) {
            *(float4*)&Ws[wr + p * 8][wn] = *(const float4*)&Wbot[(size_t)(k0 + wr + p * 8) * HID + wn];
        }
        __syncthreads();

#pragma unroll
        for (int kk = 0; kk < GBK; kk++) {
            float a[8];
            u64t b2[4];
            *(float4*)(a)     = *(const float4*)&As[kk][ty * 8];
            *(float4*)(a + 4) = *(const float4*)&As[kk][ty * 8 + 4];
            ulonglong2 t0 = *(const ulonglong2*)&Ws[kk][tx * 8];
            ulonglong2 t1 = *(const ulonglong2*)&Ws[kk][tx * 8 + 4];
            b2[0] = t0.x; b2[1] = t0.y; b2[2] = t1.x; b2[3] = t1.y;
#pragma unroll
            for (int i = 0; i < 8; i++) {
                u64t ad = dup2(a[i]);
#pragma unroll
                for (int j = 0; j < 4; j++) ffma2(acc2[i][j], ad, b2[j]);
            }
        }
        __syncthreads();
    }

#pragma unroll
    for (int i = 0; i < 8; i++) {
        int row = bm + ty * 8 + i;
        if (row < n) {
#pragma unroll
            for (int j = 0; j < 4; j++) {
                float2 f = unpack2(acc2[i][j]);
                int col = tx * 8 + j * 2;
                float c0 = C[(size_t)row * HID + col];
                float c1 = C[(size_t)row * HID + col + 1];
                C[(size_t)row * HID + col]     = fmaxf(c0 + f.x, 0.f);
                C[(size_t)row * HID + col + 1] = fmaxf(c1 + f.y, 0.f);
            }
        }
    }
}

// ---------------- segment max over contiguous graph blocks ----------------
__global__ void k_segmax(int gsize) {
    __shared__ float sm[8][HID];
    int g = blockIdx.x;
    int warp = threadIdx.x >> 5;
    int lane = threadIdx.x & 31;
    float4 m = make_float4(0.f, 0.f, 0.f, 0.f);  // relu output >= 0
    int r0 = g * gsize;
    for (int r = r0 + warp; r < r0 + gsize; r += 8) {
        float4 v = *(const float4*)&g_h2[(size_t)r * HID + lane * 4];
        m.x = fmaxf(m.x, v.x);
        m.y = fmaxf(m.y, v.y);
        m.z = fmaxf(m.z, v.z);
        m.w = fmaxf(m.w, v.w);
    }
    *(float4*)&sm[warp][lane * 4] = m;
    __syncthreads();
    if (threadIdx.x < HID) {
        int f = threadIdx.x;
        float mm = sm[0][f];
#pragma unroll
        for (int w = 1; w < 8; w++) mm = fmaxf(mm, sm[w][f]);
        g_hg[g * HID + f] = mm;
    }
}

// ---------------- classifier head ----------------
__global__ void k_final(const float* __restrict__ Wc, const float* __restrict__ bc,
                        float* __restrict__ out, int nb) {
    int t = blockIdx.x * blockDim.x + threadIdx.x;
    if (t >= nb * 10) return;
    int g = t / 10;
    int c = t % 10;
    float acc = bc[c];
#pragma unroll 8
    for (int k = 0; k < HID; k++) acc += g_hg[g * HID + k] * Wc[k * 10 + c];
    out[t] = acc;
}

// ---------------- launch ----------------
extern "C" void kernel_launch(void* const* d_in, const int* in_sizes, int n_in,
                              void* d_out, int out_size) {
    const float* x   = (const float*)d_in[0];
    const float* W1  = (const float*)d_in[1];
    const float* b1  = (const float*)d_in[2];
    const float* W2  = (const float*)d_in[3];
    const float* b2  = (const float*)d_in[4];
    const float* Wc  = (const float*)d_in[5];
    const float* bc  = (const float*)d_in[6];
    const int*   src = (const int*)d_in[7];
    const int*   dst = (const int*)d_in[8];
    float* out = (float*)d_out;

    int e = in_sizes[7];
    int n = in_sizes[9];
    int nb_graphs = out_size / 10;
    int gsize = n / nb_graphs;
    int nbscan = (n + 1023) / 1024;

    int nGemm = (n + GBM - 1) / GBM;
    int nSpmm = (n + 7) / 8;    // always <= nGemm * 16

    k_zero_deg<<<(n + 511) / 512, 512>>>(n);
    k_hist<<<(e + 511) / 512, 512>>>(dst, e);
    k_scanA<<<nbscan, 1024>>>(n);
    k_scanB<<<1, NB_SCAN>>>(nbscan);
    k_scanC<<<nbscan, 1024>>>(n, e);
    k_fill<<<(e + 511) / 512, 512>>>(src, dst, e);

    // layer 1 (writes g_h1 internally)
    k_phaseA<<<nGemm * ILV, 256>>>(0, x, W1, b1, n, nSpmm);
    k_phaseB<<<nGemm, 256>>>(0, W1 + (size_t)HID * HID, n);
    // layer 2 (reads g_h1, writes g_h2 internally)
    k_phaseA<<<nGemm * ILV, 256>>>(1, x, W2, b2, n, nSpmm);
    k_phaseB<<<nGemm, 256>>>(1, W2 + (size_t)HID * HID, n);

    k_segmax<<<nb_graphs, 256>>>(gsize);
    k_final<<<1, 512>>>(Wc, bc, out, nb_graphs);
}

// round 6
// speedup vs baseline: 1.9667x; 1.9667x over previous
#include <cuda_runtime.h>
#include <cstdint>

#define N_NODES 100000
#define E_MAX   1600000
#define HID     128
#define NB_SCAN 128
#define GBM 128

typedef unsigned long long u64t;
typedef unsigned int u32t;

// ---------------- device scratch (no allocations allowed) ----------------
__device__ int   g_deg[N_NODES];
__device__ int   g_rowptr[N_NODES + 1];
__device__ int   g_fill[N_NODES];
__device__ int   g_bsum[NB_SCAN];
__device__ int   g_boff[NB_SCAN];
__device__ int   g_col[E_MAX];
__device__ float g_dinv[N_NODES];
__device__ float g_tx1[(size_t)N_NODES * HID];
__device__ float g_h1 [(size_t)N_NODES * HID];
__device__ float g_h2 [(size_t)N_NODES * HID];
__device__ float g_hg [64 * HID];
// W transposed + tf32 hi/lo split: [layer][n=128][k=256]
__device__ u32t  g_Wthi[2 * HID * 2 * HID];
__device__ u32t  g_Wtlo[2 * HID * 2 * HID];

// ---------------- tf32 helpers ----------------
__device__ __forceinline__ u32t f2tf32(float f) {
    u32t u; asm("cvt.rna.tf32.f32 %0, %1;" : "=r"(u) : "f"(f)); return u;
}
__device__ __forceinline__ void mma_tf32(float* c, const u32t* a, const u32t* b) {
    asm volatile("mma.sync.aligned.m16n8k8.row.col.f32.tf32.tf32.f32 "
        "{%0,%1,%2,%3}, {%4,%5,%6,%7}, {%8,%9}, {%0,%1,%2,%3};"
        : "+f"(c[0]), "+f"(c[1]), "+f"(c[2]), "+f"(c[3])
        : "r"(a[0]), "r"(a[1]), "r"(a[2]), "r"(a[3]), "r"(b[0]), "r"(b[1]));
}

// ---------------- prep ----------------
__global__ void k_zero_deg(int n) {
    int i = blockIdx.x * blockDim.x + threadIdx.x;
    if (i < n) g_deg[i] = 0;
}

__global__ void k_hist(const int* __restrict__ dst, int e) {
    int i = blockIdx.x * blockDim.x + threadIdx.x;
    if (i < e) atomicAdd(&g_deg[dst[i]], 1);
}

__global__ void k_scanA(int n) {
    __shared__ int s[1024];
    int tid = threadIdx.x;
    int i = blockIdx.x * 1024 + tid;
    int v = (i < n) ? g_deg[i] : 0;
    s[tid] = v;
    __syncthreads();
    for (int off = 1; off < 1024; off <<= 1) {
        int t = (tid >= off) ? s[tid - off] : 0;
        __syncthreads();
        s[tid] += t;
        __syncthreads();
    }
    if (i < n) g_rowptr[i] = s[tid] - v;
    if (tid == 1023) g_bsum[blockIdx.x] = s[1023];
}

__global__ void k_scanB(int nb) {
    __shared__ int s[NB_SCAN];
    int tid = threadIdx.x;
    int v = (tid < nb) ? g_bsum[tid] : 0;
    s[tid] = v;
    __syncthreads();
    for (int off = 1; off < NB_SCAN; off <<= 1) {
        int t = (tid >= off) ? s[tid - off] : 0;
        __syncthreads();
        s[tid] += t;
        __syncthreads();
    }
    s[tid] -= v;
    g_boff[tid] = s[tid];
}

__global__ void k_scanC(int n, int e) {
    int i = blockIdx.x * 1024 + threadIdx.x;
    if (i < n) {
        int rp = g_rowptr[i] + g_boff[i >> 10];
        g_rowptr[i] = rp;
        g_fill[i]   = rp;
        g_dinv[i]   = rsqrtf(fmaxf((float)g_deg[i], 1.0f));
        if (i == n - 1) g_rowptr[n] = e;
    }
}

__global__ void k_fill(const int* __restrict__ src, const int* __restrict__ dst, int e) {
    int i = blockIdx.x * blockDim.x + threadIdx.x;
    if (i < e) {
        int p = atomicAdd(&g_fill[dst[i]], 1);
        g_col[p] = src[i];
    }
}

// ---------------- W prep: transpose + tf32 hi/lo split ----------------
// g_Wt*[l][n][k] from W[l][k][n]; 2 layers x 256k x 128n = 65536 elements.
__global__ void k_wprep(const float* __restrict__ W1, const float* __restrict__ W2) {
    int i = blockIdx.x * 256 + threadIdx.x;
    int l = i >> 15;
    int r = i & 32767;
    int nn = r >> 8;    // 0..127
    int kk = r & 255;   // 0..255
    float v = (l ? W2 : W1)[(size_t)kk * HID + nn];
    u32t hb = f2tf32(v);
    float hf = __uint_as_float(hb);
    u32t lb = f2tf32(v - hf);
    int o = l * 32768 + nn * 256 + kk;
    g_Wthi[o] = hb;
    g_Wtlo[o] = lb;
}

// ---------------- SpMM (round-2 proven) ----------------
__global__ void k_spmm(int layer, const float* __restrict__ xin, int n) {
    const float* __restrict__ feat = (layer == 0) ? xin : g_h1;
    int row = blockIdx.x * 8 + (threadIdx.x >> 5);
    if (row >= n) return;
    int lane = threadIdx.x & 31;
    int e0 = g_rowptr[row];
    int e1 = g_rowptr[row + 1];
    float4 acc = make_float4(0.f, 0.f, 0.f, 0.f);
    for (int e = e0; e < e1; e++) {
        int s = g_col[e];
        float w = g_dinv[s];
        float4 v = *(const float4*)&feat[(size_t)s * HID + lane * 4];
        acc.x += w * v.x;
        acc.y += w * v.y;
        acc.z += w * v.z;
        acc.w += w * v.w;
    }
    float sc = -g_dinv[row];
    acc.x *= sc; acc.y *= sc; acc.z *= sc; acc.w *= sc;
    *(float4*)&g_tx1[(size_t)row * HID + lane * 4] = acc;
}

// ---------------- tensor-core GEMM: C = relu([Afeat | g_tx1] @ W + b) ----------------
// tf32x3 split precision: Ahi*Whi + Ahi*Wlo + Alo*Whi, fp32 accumulate.
// Tile 128x128, BK=16, 8 warps (2m x 4n), warp tile 64x32 of m16n8k8.
#define TKB 16
#define SASTR 20   // padded row stride in u32 (conflict-free: gcd analysis mod 32)
__global__ __launch_bounds__(256, 2) void k_gemm_tc(int layer,
                                                    const float* __restrict__ xin,
                                                    const float* __restrict__ bias,
                                                    int n) {
    const float* __restrict__ Afeat = (layer == 0) ? xin : g_h1;
    float* __restrict__ C = (layer == 0) ? g_h1 : g_h2;
    const u32t* __restrict__ Whi = &g_Wthi[layer * 32768];
    const u32t* __restrict__ Wlo = &g_Wtlo[layer * 32768];

    __shared__ u32t As_hi[GBM][SASTR];
    __shared__ u32t As_lo[GBM][SASTR];
    __shared__ u32t Ws_hi[HID][SASTR];
    __shared__ u32t Ws_lo[HID][SASTR];

    int tid  = threadIdx.x;
    int lane = tid & 31;
    int wid  = tid >> 5;
    int wm   = wid & 1;          // 0..1 -> 64 rows
    int wn   = wid >> 1;         // 0..3 -> 32 cols
    int lr   = lane >> 2;        // 0..7
    int lc   = lane & 3;         // 0..3
    int bm   = blockIdx.x * GBM;

    float acc[4][4][4];
#pragma unroll
    for (int mi = 0; mi < 4; mi++)
#pragma unroll
        for (int ni = 0; ni < 4; ni++)
#pragma unroll
            for (int q = 0; q < 4; q++) acc[mi][ni][q] = 0.f;

    int tr = tid >> 2;           // 0..63
    int tk = (tid & 3) * 4;      // 0,4,8,12

    for (int kb = 0; kb < 2 * HID / TKB; kb++) {
        int kg = kb * TKB;
        const float* __restrict__ A = (kg < HID) ? Afeat : g_tx1;
        int kcol = (kg & (HID - 1)) + tk;

        // fill A (hi/lo split) and W tiles
#pragma unroll
        for (int p = 0; p < 2; p++) {
            int rl = tr + p * 64;
            int row = bm + rl;
            float4 v = make_float4(0.f, 0.f, 0.f, 0.f);
            if (row < n) v = *(const float4*)&A[(size_t)row * HID + kcol];
            u32t hx = f2tf32(v.x), hy = f2tf32(v.y), hz = f2tf32(v.z), hw = f2tf32(v.w);
            uint4 h = make_uint4(hx, hy, hz, hw);
            uint4 lo = make_uint4(f2tf32(v.x - __uint_as_float(hx)),
                                  f2tf32(v.y - __uint_as_float(hy)),
                                  f2tf32(v.z - __uint_as_float(hz)),
                                  f2tf32(v.w - __uint_as_float(hw)));
            *(uint4*)&As_hi[rl][tk] = h;
            *(uint4*)&As_lo[rl][tk] = lo;
            // W: rows are n (0..127), cols are k
            *(uint4*)&Ws_hi[rl][tk] = *(const uint4*)&Whi[rl * 256 + kg + tk];
            *(uint4*)&Ws_lo[rl][tk] = *(const uint4*)&Wlo[rl * 256 + kg + tk];
        }
        __syncthreads();

#pragma unroll
        for (int ks = 0; ks < 2; ks++) {
            int kk = ks * 8;
            // B fragments for all 4 n-tiles
            u32t bh[4][2], bl[4][2];
#pragma unroll
            for (int ni = 0; ni < 4; ni++) {
                int n0 = wn * 32 + ni * 8 + lr;
                bh[ni][0] = Ws_hi[n0][kk + lc];
                bh[ni][1] = Ws_hi[n0][kk + lc + 4];
                bl[ni][0] = Ws_lo[n0][kk + lc];
                bl[ni][1] = Ws_lo[n0][kk + lc + 4];
            }
#pragma unroll
            for (int mi = 0; mi < 4; mi++) {
                int m0 = wm * 64 + mi * 16;
                u32t ah[4], al[4];
                ah[0] = As_hi[m0 + lr][kk + lc];
                ah[1] = As_hi[m0 + lr + 8][kk + lc];
                ah[2] = As_hi[m0 + lr][kk + lc + 4];
                ah[3] = As_hi[m0 + lr + 8][kk + lc + 4];
                al[0] = As_lo[m0 + lr][kk + lc];
                al[1] = As_lo[m0 + lr + 8][kk + lc];
                al[2] = As_lo[m0 + lr][kk + lc + 4];
                al[3] = As_lo[m0 + lr + 8][kk + lc + 4];
#pragma unroll
                for (int ni = 0; ni < 4; ni++) {
                    mma_tf32(acc[mi][ni], ah, bh[ni]);  // hi*hi
                    mma_tf32(acc[mi][ni], ah, bl[ni]);  // hi*lo
                    mma_tf32(acc[mi][ni], al, bh[ni]);  // lo*hi
                }
            }
        }
        __syncthreads();
    }

    // epilogue: bias + relu
#pragma unroll
    for (int mi = 0; mi < 4; mi++) {
        int r0 = bm + wm * 64 + mi * 16 + lr;
        int r1 = r0 + 8;
#pragma unroll
        for (int ni = 0; ni < 4; ni++) {
            int col = wn * 32 + ni * 8 + lc * 2;
            float2 bv = *(const float2*)&bias[col];
            if (r0 < n) {
                float2 o;
                o.x = fmaxf(acc[mi][ni][0] + bv.x, 0.f);
                o.y = fmaxf(acc[mi][ni][1] + bv.y, 0.f);
                *(float2*)&C[(size_t)r0 * HID + col] = o;
            }
            if (r1 < n) {
                float2 o;
                o.x = fmaxf(acc[mi][ni][2] + bv.x, 0.f);
                o.y = fmaxf(acc[mi][ni][3] + bv.y, 0.f);
                *(float2*)&C[(size_t)r1 * HID + col] = o;
            }
        }
    }
}

// ---------------- segment max over contiguous graph blocks ----------------
__global__ void k_segmax(int gsize) {
    __shared__ float sm[8][HID];
    int g = blockIdx.x;
    int warp = threadIdx.x >> 5;
    int lane = threadIdx.x & 31;
    float4 m = make_float4(0.f, 0.f, 0.f, 0.f);  // relu output >= 0
    int r0 = g * gsize;
    for (int r = r0 + warp; r < r0 + gsize; r += 8) {
        float4 v = *(const float4*)&g_h2[(size_t)r * HID + lane * 4];
        m.x = fmaxf(m.x, v.x);
        m.y = fmaxf(m.y, v.y);
        m.z = fmaxf(m.z, v.z);
        m.w = fmaxf(m.w, v.w);
    }
    *(float4*)&sm[warp][lane * 4] = m;
    __syncthreads();
    if (threadIdx.x < HID) {
        int f = threadIdx.x;
        float mm = sm[0][f];
#pragma unroll
        for (int w = 1; w < 8; w++) mm = fmaxf(mm, sm[w][f]);
        g_hg[g * HID + f] = mm;
    }
}

// ---------------- classifier head ----------------
__global__ void k_final(const float* __restrict__ Wc, const float* __restrict__ bc,
                        float* __restrict__ out, int nb) {
    int t = blockIdx.x * blockDim.x + threadIdx.x;
    if (t >= nb * 10) return;
    int g = t / 10;
    int c = t % 10;
    float acc = bc[c];
#pragma unroll 8
    for (int k = 0; k < HID; k++) acc += g_hg[g * HID + k] * Wc[k * 10 + c];
    out[t] = acc;
}

// ---------------- launch ----------------
extern "C" void kernel_launch(void* const* d_in, const int* in_sizes, int n_in,
                              void* d_out, int out_size) {
    const float* x   = (const float*)d_in[0];
    const float* W1  = (const float*)d_in[1];
    const float* b1  = (const float*)d_in[2];
    const float* W2  = (const float*)d_in[3];
    const float* b2  = (const float*)d_in[4];
    const float* Wc  = (const float*)d_in[5];
    const float* bc  = (const float*)d_in[6];
    const int*   src = (const int*)d_in[7];
    const int*   dst = (const int*)d_in[8];
    float* out = (float*)d_out;

    int e = in_sizes[7];
    int n = in_sizes[9];
    int nb_graphs = out_size / 10;
    int gsize = n / nb_graphs;
    int nbscan = (n + 1023) / 1024;
    int nGemm = (n + GBM - 1) / GBM;

    k_zero_deg<<<(n + 511) / 512, 512>>>(n);
    k_hist<<<(e + 511) / 512, 512>>>(dst, e);
    k_wprep<<<256, 256>>>(W1, W2);
    k_scanA<<<nbscan, 1024>>>(n);
    k_scanB<<<1, NB_SCAN>>>(nbscan);
    k_scanC<<<nbscan, 1024>>>(n, e);
    k_fill<<<(e + 511) / 512, 512>>>(src, dst, e);

    // layer 1
    k_spmm<<<(n + 7) / 8, 256>>>(0, x, n);
    k_gemm_tc<<<nGemm, 256>>>(0, x, b1, n);
    // layer 2
    k_spmm<<<(n + 7) / 8, 256>>>(1, x, n);
    k_gemm_tc<<<nGemm, 256>>>(1, x, b2, n);

    k_segmax<<<nb_graphs, 256>>>(gsize);
    k_final<<<1, 512>>>(Wc, bc, out, nb_graphs);
}

// round 7
// speedup vs baseline: 2.5015x; 1.2719x over previous
#include <cuda_runtime.h>
#include <cuda_bf16.h>
#include <cstdint>

#define N_NODES 100000
#define E_MAX   1600000
#define HID     128
#define NB_SCAN 128
#define GBM 128

typedef unsigned long long u64t;
typedef unsigned int u32t;

// ---------------- device scratch (no allocations allowed) ----------------
__device__ int   g_deg[N_NODES];
__device__ int   g_rowptr[N_NODES + 1];
__device__ int   g_fill[N_NODES];
__device__ int   g_bsum[NB_SCAN];
__device__ int   g_boff[NB_SCAN];
__device__ int   g_col[E_MAX];
__device__ float g_dinv[N_NODES];
__device__ float g_tx1[(size_t)N_NODES * HID];
__device__ float g_h1 [(size_t)N_NODES * HID];
__device__ float g_h2 [(size_t)N_NODES * HID];
__device__ float g_hg [64 * HID];
// W transposed + bf16 hi/lo split, packed pairs: [layer][n=128][k2=128] u32
__device__ u32t  g_Wbhi[2 * HID * HID];
__device__ u32t  g_Wblo[2 * HID * HID];

// ---------------- bf16 helpers ----------------
__device__ __forceinline__ u32t pack_bf16(float lo_val, float hi_val) {
    // result low 16 bits = lo_val, high 16 bits = hi_val
    u32t r;
    asm("cvt.rn.bf16x2.f32 %0, %1, %2;" : "=r"(r) : "f"(hi_val), "f"(lo_val));
    return r;
}
__device__ __forceinline__ void mma_bf16(float* c, const u32t* a, const u32t* b) {
    asm volatile("mma.sync.aligned.m16n8k16.row.col.f32.bf16.bf16.f32 "
        "{%0,%1,%2,%3}, {%4,%5,%6,%7}, {%8,%9}, {%0,%1,%2,%3};"
        : "+f"(c[0]), "+f"(c[1]), "+f"(c[2]), "+f"(c[3])
        : "r"(a[0]), "r"(a[1]), "r"(a[2]), "r"(a[3]), "r"(b[0]), "r"(b[1]));
}

// ---------------- prep ----------------
__global__ void k_zero_deg(int n) {
    int i = blockIdx.x * blockDim.x + threadIdx.x;
    if (i < n) g_deg[i] = 0;
}

__global__ void k_hist(const int* __restrict__ dst, int e) {
    int i = blockIdx.x * blockDim.x + threadIdx.x;
    if (i < e) atomicAdd(&g_deg[dst[i]], 1);
}

__global__ void k_scanA(int n) {
    __shared__ int s[1024];
    int tid = threadIdx.x;
    int i = blockIdx.x * 1024 + tid;
    int v = (i < n) ? g_deg[i] : 0;
    s[tid] = v;
    __syncthreads();
    for (int off = 1; off < 1024; off <<= 1) {
        int t = (tid >= off) ? s[tid - off] : 0;
        __syncthreads();
        s[tid] += t;
        __syncthreads();
    }
    if (i < n) g_rowptr[i] = s[tid] - v;
    if (tid == 1023) g_bsum[blockIdx.x] = s[1023];
}

__global__ void k_scanB(int nb) {
    __shared__ int s[NB_SCAN];
    int tid = threadIdx.x;
    int v = (tid < nb) ? g_bsum[tid] : 0;
    s[tid] = v;
    __syncthreads();
    for (int off = 1; off < NB_SCAN; off <<= 1) {
        int t = (tid >= off) ? s[tid - off] : 0;
        __syncthreads();
        s[tid] += t;
        __syncthreads();
    }
    s[tid] -= v;
    g_boff[tid] = s[tid];
}

__global__ void k_scanC(int n, int e) {
    int i = blockIdx.x * 1024 + threadIdx.x;
    if (i < n) {
        int rp = g_rowptr[i] + g_boff[i >> 10];
        g_rowptr[i] = rp;
        g_fill[i]   = rp;
        g_dinv[i]   = rsqrtf(fmaxf((float)g_deg[i], 1.0f));
        if (i == n - 1) g_rowptr[n] = e;
    }
}

__global__ void k_fill(const int* __restrict__ src, const int* __restrict__ dst, int e) {
    int i = blockIdx.x * blockDim.x + threadIdx.x;
    if (i < e) {
        int p = atomicAdd(&g_fill[dst[i]], 1);
        g_col[p] = src[i];
    }
}

// ---------------- W prep: transpose + bf16 hi/lo split, packed k-pairs ----------------
// From W[l][k=256][n=128] to g_Wb*[l][n][k2=128] (u32 = 2 consecutive-k bf16s).
__global__ void k_wprep(const float* __restrict__ W1, const float* __restrict__ W2) {
    int i = blockIdx.x * 256 + threadIdx.x;   // 0..32767
    int l  = i >> 14;
    int r  = i & 16383;
    int nn = r >> 7;     // 0..127
    int k2 = r & 127;    // 0..127
    const float* Wl = l ? W2 : W1;
    float v0 = Wl[(size_t)(2 * k2) * HID + nn];
    float v1 = Wl[(size_t)(2 * k2 + 1) * HID + nn];
    __nv_bfloat16 h0 = __float2bfloat16_rn(v0);
    __nv_bfloat16 h1 = __float2bfloat16_rn(v1);
    float l0 = v0 - __bfloat162float(h0);
    float l1 = v1 - __bfloat162float(h1);
    int o = l * (HID * HID) + nn * 128 + k2;
    g_Wbhi[o] = pack_bf16(__bfloat162float(h0), __bfloat162float(h1));
    g_Wblo[o] = pack_bf16(l0, l1);
}

// ---------------- SpMM (round-2 proven) ----------------
__global__ void k_spmm(int layer, const float* __restrict__ xin, int n) {
    const float* __restrict__ feat = (layer == 0) ? xin : g_h1;
    int row = blockIdx.x * 8 + (threadIdx.x >> 5);
    if (row >= n) return;
    int lane = threadIdx.x & 31;
    int e0 = g_rowptr[row];
    int e1 = g_rowptr[row + 1];
    float4 acc = make_float4(0.f, 0.f, 0.f, 0.f);
    for (int e = e0; e < e1; e++) {
        int s = g_col[e];
        float w = g_dinv[s];
        float4 v = *(const float4*)&feat[(size_t)s * HID + lane * 4];
        acc.x += w * v.x;
        acc.y += w * v.y;
        acc.z += w * v.z;
        acc.w += w * v.w;
    }
    float sc = -g_dinv[row];
    acc.x *= sc; acc.y *= sc; acc.z *= sc; acc.w *= sc;
    *(float4*)&g_tx1[(size_t)row * HID + lane * 4] = acc;
}

// ---------------- tensor GEMM: C = relu([Afeat | g_tx1] @ W + b) ----------------
// bf16x3 split: Ahi*Whi + Ahi*Wlo + Alo*Whi, fp32 accumulate, m16n8k16.
// Tile 128x128, BK=32 (2 x k16 halves), 8 warps (2m x 4n), warp tile 64x32.
// smem: [half][row][8 u32], col XOR-swizzled by (row&6).
__global__ __launch_bounds__(256, 2) void k_gemm_tc(int layer,
                                                    const float* __restrict__ xin,
                                                    const float* __restrict__ bias,
                                                    int n) {
    const float* __restrict__ Afeat = (layer == 0) ? xin : g_h1;
    float* __restrict__ C = (layer == 0) ? g_h1 : g_h2;
    const u32t* __restrict__ Whi = &g_Wbhi[layer * (HID * HID)];
    const u32t* __restrict__ Wlo = &g_Wblo[layer * (HID * HID)];

    __shared__ u32t As_hi[2][GBM][8];
    __shared__ u32t As_lo[2][GBM][8];
    __shared__ u32t Ws_hi[2][HID][8];
    __shared__ u32t Ws_lo[2][HID][8];

    int tid  = threadIdx.x;
    int lane = tid & 31;
    int wid  = tid >> 5;
    int wm   = wid & 1;          // 0..1 -> 64-row half
    int wn   = wid >> 1;         // 0..3 -> 32-col quarter
    int lr   = lane >> 2;        // 0..7
    int lc   = lane & 3;         // 0..3
    int bm   = blockIdx.x * GBM;
    int swl  = lr & 6;           // fragment-read swizzle
    int ca   = lc ^ swl;         // low-k col, high-k col = ca^4

    float acc[4][4][4];
#pragma unroll
    for (int mi = 0; mi < 4; mi++)
#pragma unroll
        for (int ni = 0; ni < 4; ni++)
#pragma unroll
            for (int q = 0; q < 4; q++) acc[mi][ni][q] = 0.f;

    int tr = tid >> 2;           // 0..63 (fill row base)
    int tq = tid & 3;            // 0..3  (fill k sub-offset)

    for (int kb = 0; kb < 8; kb++) {
        int kg = kb * 32;
        const float* __restrict__ A = (kg < HID) ? Afeat : g_tx1;
        int kcol = kg & (HID - 1);

#pragma unroll
        for (int h = 0; h < 2; h++) {
#pragma unroll
            for (int p = 0; p < 2; p++) {
                int rl = tr + p * 64;
                int sw = rl & 6;
                int cc = (tq * 2) ^ sw;
                // A: load 4 floats, split to bf16 hi/lo pairs
                int row = bm + rl;
                float4 v = make_float4(0.f, 0.f, 0.f, 0.f);
                if (row < n) v = *(const float4*)&A[(size_t)row * HID + kcol + h * 16 + tq * 4];
                __nv_bfloat16 bx = __float2bfloat16_rn(v.x);
                __nv_bfloat16 by = __float2bfloat16_rn(v.y);
                __nv_bfloat16 bz = __float2bfloat16_rn(v.z);
                __nv_bfloat16 bw = __float2bfloat16_rn(v.w);
                float fx = __bfloat162float(bx), fy = __bfloat162float(by);
                float fz = __bfloat162float(bz), fw = __bfloat162float(bw);
                uint2 hi = make_uint2(pack_bf16(fx, fy), pack_bf16(fz, fw));
                uint2 lo = make_uint2(pack_bf16(v.x - fx, v.y - fy),
                                      pack_bf16(v.z - fz, v.w - fw));
                *(uint2*)&As_hi[h][rl][cc] = hi;
                *(uint2*)&As_lo[h][rl][cc] = lo;
                // W: already packed in global
                int wo = rl * 128 + (kg + h * 16) / 2 + tq * 2;
                *(uint2*)&Ws_hi[h][rl][cc] = *(const uint2*)&Whi[wo];
                *(uint2*)&Ws_lo[h][rl][cc] = *(const uint2*)&Wlo[wo];
            }
        }
        __syncthreads();

#pragma unroll
        for (int h = 0; h < 2; h++) {
            u32t bh[4][2], bl[4][2];
#pragma unroll
            for (int ni = 0; ni < 4; ni++) {
                int n0 = wn * 32 + ni * 8 + lr;
                bh[ni][0] = Ws_hi[h][n0][ca];
                bh[ni][1] = Ws_hi[h][n0][ca ^ 4];
                bl[ni][0] = Ws_lo[h][n0][ca];
                bl[ni][1] = Ws_lo[h][n0][ca ^ 4];
            }
#pragma unroll
            for (int mi = 0; mi < 4; mi++) {
                int m0 = wm * 64 + mi * 16;
                u32t ah[4], al[4];
                ah[0] = As_hi[h][m0 + lr][ca];
                ah[1] = As_hi[h][m0 + lr + 8][ca];
                ah[2] = As_hi[h][m0 + lr][ca ^ 4];
                ah[3] = As_hi[h][m0 + lr + 8][ca ^ 4];
                al[0] = As_lo[h][m0 + lr][ca];
                al[1] = As_lo[h][m0 + lr + 8][ca];
                al[2] = As_lo[h][m0 + lr][ca ^ 4];
                al[3] = As_lo[h][m0 + lr + 8][ca ^ 4];
#pragma unroll
                for (int ni = 0; ni < 4; ni++) {
                    mma_bf16(acc[mi][ni], ah, bh[ni]);  // hi*hi
                    mma_bf16(acc[mi][ni], ah, bl[ni]);  // hi*lo
                    mma_bf16(acc[mi][ni], al, bh[ni]);  // lo*hi
                }
            }
        }
        __syncthreads();
    }

    // epilogue: bias + relu (C fragment: c0,c1 row lr col 2lc,2lc+1; c2,c3 row lr+8)
#pragma unroll
    for (int mi = 0; mi < 4; mi++) {
        int r0 = bm + wm * 64 + mi * 16 + lr;
        int r1 = r0 + 8;
#pragma unroll
        for (int ni = 0; ni < 4; ni++) {
            int col = wn * 32 + ni * 8 + lc * 2;
            float2 bv = *(const float2*)&bias[col];
            if (r0 < n) {
                float2 o;
                o.x = fmaxf(acc[mi][ni][0] + bv.x, 0.f);
                o.y = fmaxf(acc[mi][ni][1] + bv.y, 0.f);
                *(float2*)&C[(size_t)r0 * HID + col] = o;
            }
            if (r1 < n) {
                float2 o;
                o.x = fmaxf(acc[mi][ni][2] + bv.x, 0.f);
                o.y = fmaxf(acc[mi][ni][3] + bv.y, 0.f);
                *(float2*)&C[(size_t)r1 * HID + col] = o;
            }
        }
    }
}

// ---------------- segment max over contiguous graph blocks ----------------
__global__ void k_segmax(int gsize) {
    __shared__ float sm[8][HID];
    int g = blockIdx.x;
    int warp = threadIdx.x >> 5;
    int lane = threadIdx.x & 31;
    float4 m = make_float4(0.f, 0.f, 0.f, 0.f);  // relu output >= 0
    int r0 = g * gsize;
    for (int r = r0 + warp; r < r0 + gsize; r += 8) {
        float4 v = *(const float4*)&g_h2[(size_t)r * HID + lane * 4];
        m.x = fmaxf(m.x, v.x);
        m.y = fmaxf(m.y, v.y);
        m.z = fmaxf(m.z, v.z);
        m.w = fmaxf(m.w, v.w);
    }
    *(float4*)&sm[warp][lane * 4] = m;
    __syncthreads();
    if (threadIdx.x < HID) {
        int f = threadIdx.x;
        float mm = sm[0][f];
#pragma unroll
        for (int w = 1; w < 8; w++) mm = fmaxf(mm, sm[w][f]);
        g_hg[g * HID + f] = mm;
    }
}

// ---------------- classifier head ----------------
__global__ void k_final(const float* __restrict__ Wc, const float* __restrict__ bc,
                        float* __restrict__ out, int nb) {
    int t = blockIdx.x * blockDim.x + threadIdx.x;
    if (t >= nb * 10) return;
    int g = t / 10;
    int c = t % 10;
    float acc = bc[c];
#pragma unroll 8
    for (int k = 0; k < HID; k++) acc += g_hg[g * HID + k] * Wc[k * 10 + c];
    out[t] = acc;
}

// ---------------- launch ----------------
extern "C" void kernel_launch(void* const* d_in, const int* in_sizes, int n_in,
                              void* d_out, int out_size) {
    const float* x   = (const float*)d_in[0];
    const float* W1  = (const float*)d_in[1];
    const float* b1  = (const float*)d_in[2];
    const float* W2  = (const float*)d_in[3];
    const float* b2  = (const float*)d_in[4];
    const float* Wc  = (const float*)d_in[5];
    const float* bc  = (const float*)d_in[6];
    const int*   src = (const int*)d_in[7];
    const int*   dst = (const int*)d_in[8];
    float* out = (float*)d_out;

    int e = in_sizes[7];
    int n = in_sizes[9];
    int nb_graphs = out_size / 10;
    int gsize = n / nb_graphs;
    int nbscan = (n + 1023) / 1024;
    int nGemm = (n + GBM - 1) / GBM;

    k_zero_deg<<<(n + 511) / 512, 512>>>(n);
    k_hist<<<(e + 511) / 512, 512>>>(dst, e);
    k_wprep<<<128, 256>>>(W1, W2);
    k_scanA<<<nbscan, 1024>>>(n);
    k_scanB<<<1, NB_SCAN>>>(nbscan);
    k_scanC<<<nbscan, 1024>>>(n, e);
    k_fill<<<(e + 511) / 512, 512>>>(src, dst, e);

    // layer 1
    k_spmm<<<(n + 7) / 8, 256>>>(0, x, n);
    k_gemm_tc<<<nGemm, 256>>>(0, x, b1, n);
    // layer 2
    k_spmm<<<(n + 7) / 8, 256>>>(1, x, n);
    k_gemm_tc<<<nGemm, 256>>>(1, x, b2, n);

    k_segmax<<<nb_graphs, 256>>>(gsize);
    k_final<<<1, 512>>>(Wc, bc, out, nb_graphs);
}